// round 4
// baseline (speedup 1.0000x reference)
#include <cuda_runtime.h>
#include <cstdint>

#define NN   100000
#define NE   1600000
#define DIN  512
#define HD   128
#define DOUT 64

// ---------------- scratch (device globals: allocation-free) ----------------
__device__ float g_deg[NN];
__device__ float g_h0 [(size_t)NN * HD];
__device__ float g_h  [(size_t)NN * HD];
__device__ float g_agg[(size_t)NN * HD];
// K-major, tf32-split weights: [N][K]
__device__ float g_w1t_hi[HD * DIN],    g_w1t_lo[HD * DIN];
__device__ float g_cwt_hi[2 * HD * HD], g_cwt_lo[2 * HD * HD];
__device__ float g_w2t_hi[DOUT * HD],   g_w2t_lo[DOUT * HD];

// ======================= helpers =====================
__device__ __forceinline__ uint32_t smem_to_u32(const void* p) {
    uint32_t a;
    asm("{ .reg .u64 t; cvta.to.shared.u64 t, %1; cvt.u32.u64 %0, t; }" : "=r"(a) : "l"(p));
    return a;
}
__device__ __forceinline__ void split_tf32(float x, uint32_t& hi, uint32_t& lo) {
    asm("cvt.rna.tf32.f32 %0, %1;" : "=r"(hi) : "f"(x));
    float r = x - __uint_as_float(hi);
    asm("cvt.rna.tf32.f32 %0, %1;" : "=r"(lo) : "f"(r));
}
__device__ __forceinline__ void ldsm4(uint32_t* r, uint32_t addr) {
    asm volatile("ldmatrix.sync.aligned.m8n8.x4.shared.b16 {%0,%1,%2,%3}, [%4];"
                 : "=r"(r[0]), "=r"(r[1]), "=r"(r[2]), "=r"(r[3]) : "r"(addr));
}
__device__ __forceinline__ void mma_tf32(float* c, const uint32_t* a, const uint32_t* b) {
    asm volatile("mma.sync.aligned.m16n8k8.row.col.f32.tf32.tf32.f32 "
                 "{%0,%1,%2,%3}, {%4,%5,%6,%7}, {%8,%9}, {%0,%1,%2,%3};"
                 : "+f"(c[0]), "+f"(c[1]), "+f"(c[2]), "+f"(c[3])
                 : "r"(a[0]), "r"(a[1]), "r"(a[2]), "r"(a[3]), "r"(b[0]), "r"(b[1]));
}
__device__ __forceinline__ void cp_async16(uint32_t dst, const void* src) {
    asm volatile("cp.async.cg.shared.global [%0], [%1], 16;"
                 :: "r"(dst), "l"((unsigned long long)__cvta_generic_to_global(src)) : "memory");
}
__device__ __forceinline__ void cp_commit() {
    asm volatile("cp.async.commit_group;" ::: "memory");
}
template<int N> __device__ __forceinline__ void cp_wait() {
    asm volatile("cp.async.wait_group %0;" :: "n"(N) : "memory");
}

// ---------------- degree / dinv ----------------
__global__ void deg_init_kernel() {
    int i = blockIdx.x * blockDim.x + threadIdx.x;
    if (i < NN) g_deg[i] = 1.0f;
}
__global__ void deg_accum_kernel(const int* __restrict__ ei) {
    int e = blockIdx.x * blockDim.x + threadIdx.x;
    if (e < NE) atomicAdd(&g_deg[ei[NE + e]], 1.0f);
}
__global__ void dinv_kernel() {
    int i = blockIdx.x * blockDim.x + threadIdx.x;
    if (i < NN) g_deg[i] = rsqrtf(g_deg[i]);
}

// ---------------- weight transpose + tf32 split ----------------
__global__ void prep_weights(const float* __restrict__ w1,
                             const float* __restrict__ cw,
                             const float* __restrict__ w2) {
    int i = blockIdx.x * blockDim.x + threadIdx.x;
    const int N1 = HD * DIN;
    const int N2 = 2 * HD * HD;
    const int N3 = DOUT * HD;
    if (i < N1) {
        int n = i / DIN, k = i % DIN;
        float v = w1[(size_t)k * HD + n];
        split_tf32(v, ((uint32_t*)g_w1t_hi)[i], ((uint32_t*)g_w1t_lo)[i]);
    } else if (i < N1 + N2) {
        int j = i - N1;
        int l = j / (HD * HD), r = j % (HD * HD);
        int n = r / HD, k = r % HD;
        float v = cw[(size_t)l * HD * HD + (size_t)k * HD + n];
        split_tf32(v, ((uint32_t*)g_cwt_hi)[j], ((uint32_t*)g_cwt_lo)[j]);
    } else if (i < N1 + N2 + N3) {
        int j = i - N1 - N2;
        int n = j / HD, k = j % HD;
        float v = w2[(size_t)k * DOUT + n];
        split_tf32(v, ((uint32_t*)g_w2t_hi)[j], ((uint32_t*)g_w2t_lo)[j]);
    }
}

// ---------------- self-loop init: agg[i] = dinv[i]^2 * h[i] ----------------
__global__ void selfloop_kernel(const float* __restrict__ src) {
    int idx = blockIdx.x * blockDim.x + threadIdx.x;
    if (idx >= NN * (HD / 4)) return;
    int node = idx >> 5;
    int f    = idx & 31;
    float d = g_deg[node];
    float w = d * d;
    float4 v = ((const float4*)(src + (size_t)node * HD))[f];
    v.x *= w; v.y *= w; v.z *= w; v.w *= w;
    ((float4*)(g_agg + (size_t)node * HD))[f] = v;
}

// ---------------- edge aggregation: warp per edge ----------
__global__ void edge_kernel(const int* __restrict__ ei, const float* __restrict__ src) {
    int gid  = blockIdx.x * blockDim.x + threadIdx.x;
    int e    = gid >> 5;
    if (e >= NE) return;
    int lane = gid & 31;
    int r = __ldg(&ei[e]);
    int c = __ldg(&ei[NE + e]);
    float w = g_deg[r] * g_deg[c];
    float4 v = ((const float4*)(src + (size_t)r * HD))[lane];
    v.x *= w; v.y *= w; v.z *= w; v.w *= w;
    float4* dst = ((float4*)(g_agg + (size_t)c * HD)) + lane;
    asm volatile("red.global.add.v4.f32 [%0], {%1, %2, %3, %4};"
                 :: "l"(__cvta_generic_to_global(dst)),
                    "f"(v.x), "f"(v.y), "f"(v.z), "f"(v.w)
                 : "memory");
}

// =================== mma.sync tf32x3 GEMM ===================
// C[M,BN] = opA[M,K] @ Bt[BN,K]^T, opA = (COMBINE ? ca*A + cb*A2 : A)
// Bt pre-split K-major (hi/lo tf32-rounded fp32). BM=128, BK=16, 8 warps.
template<int BN, bool RELU, bool BIAS, bool COMBINE>
__global__ void __launch_bounds__(256, 1)
mma_gemm(const float* __restrict__ A, const float* __restrict__ A2,
         const float* __restrict__ Bhi, const float* __restrict__ Blo,
         const float* __restrict__ bias, float* __restrict__ C,
         int M, int K, float ca, float cb)
{
    constexpr int BM = 128, BK = 16, BKP = 20;      // padded stride (floats)
    constexpr int MF = 4;                           // 64/16 m-frags per warp
    constexpr int WN = BN / 4;                      // warp N extent
    constexpr int NF = WN / 8;                      // n-frags per warp (4 or 2)
    constexpr int ASZ = BM * BKP;                   // floats per A buffer
    constexpr int BSZ = BN * BKP;

    extern __shared__ float sm[];
    float* AH = sm;                  // [2][ASZ]
    float* AL = sm + 2 * ASZ;        // [2][ASZ]
    const uint32_t sb  = smem_to_u32(sm);
    const uint32_t uAH = sb;
    const uint32_t uAL = sb + 2 * ASZ * 4;
    const uint32_t uBH = sb + 4 * ASZ * 4;
    const uint32_t uBL = sb + 4 * ASZ * 4 + 2 * BSZ * 4;

    const int tid  = threadIdx.x;
    const int lane = tid & 31;
    const int wid  = tid >> 5;
    const int wm   = (wid >> 2) * 64;
    const int wn   = (wid & 3) * WN;
    const int blockM = blockIdx.x * BM;

    // ldmatrix per-thread row/col offsets
    const int lm_r = (lane & 7) + ((lane >> 3) & 1) * 8;   // row within 16
    const int lm_k = ((lane >> 4) & 1) * 4;                // col quad (0 or 4)

    float acc[MF][NF][4];
    #pragma unroll
    for (int mf = 0; mf < MF; mf++)
        #pragma unroll
        for (int nf = 0; nf < NF; nf++)
            #pragma unroll
            for (int q = 0; q < 4; q++) acc[mf][nf][q] = 0.0f;

    const int nit = K / BK;

    // ---- B tile fill via cp.async (pre-split weights, no tail) ----
    auto fillB = [&](int i, int b) {
        constexpr int CH = BN * 4;          // 16B chunks per operand
        #pragma unroll
        for (int it = 0; it < CH / 256; it++) {
            int id = tid + it * 256;
            int n  = id >> 2, c4 = id & 3;
            uint32_t off = (uint32_t)(n * BKP + c4 * 4) * 4;
            const float* gh = Bhi + (size_t)n * K + i * BK + c4 * 4;
            const float* gl = Blo + (size_t)n * K + i * BK + c4 * 4;
            cp_async16(uBH + (uint32_t)b * BSZ * 4 + off, gh);
            cp_async16(uBL + (uint32_t)b * BSZ * 4 + off, gl);
        }
    };
    // ---- A gmem load into regs (guarded, combined) ----
    float4 aR[2];
    auto loadA = [&](int i) {
        #pragma unroll
        for (int it = 0; it < 2; it++) {
            int id  = tid + it * 256;       // 0..511
            int row = id >> 2, c4 = id & 3;
            int gr  = blockM + row;
            float4 v = make_float4(0.f, 0.f, 0.f, 0.f);
            if (gr < M) {
                v = *(const float4*)(A + (size_t)gr * K + i * BK + c4 * 4);
                if (COMBINE) {
                    float4 u = *(const float4*)(A2 + (size_t)gr * K + i * BK + c4 * 4);
                    v.x = ca * v.x + cb * u.x;
                    v.y = ca * v.y + cb * u.y;
                    v.z = ca * v.z + cb * u.z;
                    v.w = ca * v.w + cb * u.w;
                }
            }
            aR[it] = v;
        }
    };
    // ---- split regs -> smem ----
    auto storeA = [&](int b) {
        #pragma unroll
        for (int it = 0; it < 2; it++) {
            int id  = tid + it * 256;
            int row = id >> 2, c4 = id & 3;
            uint4 hi, lo;
            split_tf32(aR[it].x, hi.x, lo.x);
            split_tf32(aR[it].y, hi.y, lo.y);
            split_tf32(aR[it].z, hi.z, lo.z);
            split_tf32(aR[it].w, hi.w, lo.w);
            int off = row * BKP + c4 * 4;
            *(uint4*)(AH + b * ASZ + off) = hi;
            *(uint4*)(AL + b * ASZ + off) = lo;
        }
    };
    // ---- compute one BK=16 tile ----
    auto compute = [&](int b) {
        #pragma unroll
        for (int ks = 0; ks < 2; ks++) {
            uint32_t ah[MF][4], al[MF][4];
            #pragma unroll
            for (int mf = 0; mf < MF; mf++) {
                uint32_t off = (uint32_t)((wm + mf * 16 + lm_r) * BKP + ks * 8 + lm_k) * 4;
                ldsm4(ah[mf], uAH + (uint32_t)b * ASZ * 4 + off);
                ldsm4(al[mf], uAL + (uint32_t)b * ASZ * 4 + off);
            }
            uint32_t bh[NF][2], bl[NF][2];
            #pragma unroll
            for (int nf2 = 0; nf2 < NF / 2; nf2++) {
                uint32_t off = (uint32_t)((wn + nf2 * 16 + lm_r) * BKP + ks * 8 + lm_k) * 4;
                uint32_t t[4];
                ldsm4(t, uBH + (uint32_t)b * BSZ * 4 + off);
                bh[2 * nf2][0] = t[0]; bh[2 * nf2 + 1][0] = t[1];
                bh[2 * nf2][1] = t[2]; bh[2 * nf2 + 1][1] = t[3];
                ldsm4(t, uBL + (uint32_t)b * BSZ * 4 + off);
                bl[2 * nf2][0] = t[0]; bl[2 * nf2 + 1][0] = t[1];
                bl[2 * nf2][1] = t[2]; bl[2 * nf2 + 1][1] = t[3];
            }
            #pragma unroll
            for (int mf = 0; mf < MF; mf++)
                #pragma unroll
                for (int nf = 0; nf < NF; nf++) {
                    mma_tf32(acc[mf][nf], ah[mf], bh[nf]);
                    mma_tf32(acc[mf][nf], ah[mf], bl[nf]);
                    mma_tf32(acc[mf][nf], al[mf], bh[nf]);
                }
        }
    };

    // ---- prologue: tile 0 ----
    loadA(0);
    fillB(0, 0);
    cp_commit();
    storeA(0);

    // ---- mainloop ----
    for (int i = 0; i < nit; i++) {
        const int b = i & 1;
        if (i + 1 < nit) {
            loadA(i + 1);
            fillB(i + 1, b ^ 1);
            cp_commit();
            cp_wait<1>();
        } else {
            cp_wait<0>();
        }
        __syncthreads();
        compute(b);
        if (i + 1 < nit) storeA(b ^ 1);
    }

    // ---- epilogue ----
    #pragma unroll
    for (int mf = 0; mf < MF; mf++) {
        int row0 = blockM + wm + mf * 16 + (lane >> 2);
        #pragma unroll
        for (int nf = 0; nf < NF; nf++) {
            int col = wn + nf * 8 + (lane & 3) * 2;
            float2 v0 = make_float2(acc[mf][nf][0], acc[mf][nf][1]);
            float2 v1 = make_float2(acc[mf][nf][2], acc[mf][nf][3]);
            if (BIAS) {
                float b0 = bias[col], b1 = bias[col + 1];
                v0.x += b0; v0.y += b1;
                v1.x += b0; v1.y += b1;
            }
            if (RELU) {
                v0.x = fmaxf(v0.x, 0.f); v0.y = fmaxf(v0.y, 0.f);
                v1.x = fmaxf(v1.x, 0.f); v1.y = fmaxf(v1.y, 0.f);
            }
            if (row0 < M)     *(float2*)(C + (size_t)row0 * BN + col)       = v0;
            if (row0 + 8 < M) *(float2*)(C + (size_t)(row0 + 8) * BN + col) = v1;
        }
    }
}

// ---------------- launch ----------------
extern "C" void kernel_launch(void* const* d_in, const int* in_sizes, int n_in,
                              void* d_out, int out_size)
{
    const float* x  = (const float*)d_in[0];
    const int*   ei = (const int*)  d_in[1];
    const float* w1 = (const float*)d_in[2];
    const float* b1 = (const float*)d_in[3];
    const float* cw = (const float*)d_in[4];
    const float* w2 = (const float*)d_in[5];
    const float* b2 = (const float*)d_in[6];

    float* out    = (float*)d_out;
    float* hout   = out;
    float* logits = out + (size_t)NN * HD;

    float *p_h0, *p_h, *p_agg;
    float *p_w1h, *p_w1l, *p_cwh, *p_cwl, *p_w2h, *p_w2l;
    cudaGetSymbolAddress((void**)&p_h0,  g_h0);
    cudaGetSymbolAddress((void**)&p_h,   g_h);
    cudaGetSymbolAddress((void**)&p_agg, g_agg);
    cudaGetSymbolAddress((void**)&p_w1h, g_w1t_hi);
    cudaGetSymbolAddress((void**)&p_w1l, g_w1t_lo);
    cudaGetSymbolAddress((void**)&p_cwh, g_cwt_hi);
    cudaGetSymbolAddress((void**)&p_cwl, g_cwt_lo);
    cudaGetSymbolAddress((void**)&p_w2h, g_w2t_hi);
    cudaGetSymbolAddress((void**)&p_w2l, g_w2t_lo);

    const int TPB = 256;
    const int gemm_grid = (NN + 127) / 128;                  // 782
    const int SMEM_128 = (4 * 128 * 20 + 4 * 128 * 20) * 4;  // 81920 B
    const int SMEM_64  = (4 * 128 * 20 + 4 * 64 * 20) * 4;   // 61440 B

    cudaFuncSetAttribute(mma_gemm<128, true,  true,  false>,
                         cudaFuncAttributeMaxDynamicSharedMemorySize, SMEM_128);
    cudaFuncSetAttribute(mma_gemm<128, false, false, true>,
                         cudaFuncAttributeMaxDynamicSharedMemorySize, SMEM_128);
    cudaFuncSetAttribute(mma_gemm<64,  false, true,  false>,
                         cudaFuncAttributeMaxDynamicSharedMemorySize, SMEM_64);

    // degrees -> dinv, weight prep
    deg_init_kernel <<<(NN + TPB - 1) / TPB, TPB>>>();
    deg_accum_kernel<<<(NE + TPB - 1) / TPB, TPB>>>(ei);
    dinv_kernel     <<<(NN + TPB - 1) / TPB, TPB>>>();
    prep_weights    <<<(HD*DIN + 2*HD*HD + DOUT*HD + TPB - 1) / TPB, TPB>>>(w1, cw, w2);

    // h0 = relu(x @ w1 + b1)
    mma_gemm<128, true, true, false><<<gemm_grid, 256, SMEM_128>>>(
        x, nullptr, p_w1h, p_w1l, b1, p_h0, NN, DIN, 0.f, 0.f);

    // ---- layer 1 ----
    selfloop_kernel<<<(NN * 32 + TPB - 1) / TPB, TPB>>>(p_h0);
    edge_kernel    <<<NE / 8, TPB>>>(ei, p_h0);
    mma_gemm<128, false, false, true><<<gemm_grid, 256, SMEM_128>>>(
        p_agg, p_h0, p_cwh, p_cwl, nullptr, p_h, NN, HD, 0.9f, 0.1f);

    // ---- layer 2 (writes h directly to d_out) ----
    selfloop_kernel<<<(NN * 32 + TPB - 1) / TPB, TPB>>>(p_h);
    edge_kernel    <<<NE / 8, TPB>>>(ei, p_h);
    mma_gemm<128, false, false, true><<<gemm_grid, 256, SMEM_128>>>(
        p_agg, p_h0, p_cwh + HD * HD, p_cwl + HD * HD, nullptr, hout, NN, HD, 0.9f, 0.1f);

    // logits = hout @ w2 + b2
    mma_gemm<64, false, true, false><<<gemm_grid, 256, SMEM_64>>>(
        hout, nullptr, p_w2h, p_w2l, b2, logits, NN, HD, 0.f, 0.f);
}

// round 5
// speedup vs baseline: 1.9076x; 1.9076x over previous
#include <cuda_runtime.h>
#include <cuda_fp16.h>
#include <cstdint>

#define NN   100000
#define NE   1600000
#define DIN  512
#define HD   128
#define DOUT 64

// ---------------- scratch (device globals: allocation-free) ----------------
__device__ float g_deg[NN];                     // dinv
__device__ float g_h0 [(size_t)NN * HD];
__device__ float g_h  [(size_t)NN * HD];
__device__ float g_agg[(size_t)NN * HD];
// CSR build
__device__ int g_cnt[NN];
__device__ int g_rp [NN + 1];
__device__ int g_cur[NN];
__device__ int g_csr[NE];
__device__ int g_bsum[128], g_boff[128];
// K-major, fp16-split weights: [N][K]
__device__ __half g_w1t_hi[HD * DIN],    g_w1t_lo[HD * DIN];
__device__ __half g_cwt_hi[2 * HD * HD], g_cwt_lo[2 * HD * HD];
__device__ __half g_w2t_hi[DOUT * HD],   g_w2t_lo[DOUT * HD];

// ======================= helpers =====================
__device__ __forceinline__ uint32_t smem_to_u32(const void* p) {
    uint32_t a;
    asm("{ .reg .u64 t; cvta.to.shared.u64 t, %1; cvt.u32.u64 %0, t; }" : "=r"(a) : "l"(p));
    return a;
}
__device__ __forceinline__ void ldsm4(uint32_t* r, uint32_t addr) {
    asm volatile("ldmatrix.sync.aligned.m8n8.x4.shared.b16 {%0,%1,%2,%3}, [%4];"
                 : "=r"(r[0]), "=r"(r[1]), "=r"(r[2]), "=r"(r[3]) : "r"(addr));
}
__device__ __forceinline__ void mma_f16(float* c, const uint32_t* a, const uint32_t* b) {
    asm volatile("mma.sync.aligned.m16n8k16.row.col.f32.f16.f16.f32 "
                 "{%0,%1,%2,%3}, {%4,%5,%6,%7}, {%8,%9}, {%0,%1,%2,%3};"
                 : "+f"(c[0]), "+f"(c[1]), "+f"(c[2]), "+f"(c[3])
                 : "r"(a[0]), "r"(a[1]), "r"(a[2]), "r"(a[3]), "r"(b[0]), "r"(b[1]));
}
__device__ __forceinline__ void cp_async16(uint32_t dst, const void* src) {
    asm volatile("cp.async.cg.shared.global [%0], [%1], 16;"
                 :: "r"(dst), "l"((unsigned long long)__cvta_generic_to_global(src)) : "memory");
}
__device__ __forceinline__ void cp_commit() {
    asm volatile("cp.async.commit_group;" ::: "memory");
}
template<int N> __device__ __forceinline__ void cp_wait() {
    asm volatile("cp.async.wait_group %0;" :: "n"(N) : "memory");
}
__device__ __forceinline__ void split_f16(float x, __half& hi, __half& lo) {
    hi = __float2half_rn(x);
    lo = __float2half_rn(x - __half2float(hi));
}

// ---------------- CSR build ----------------
__global__ void cnt_init_kernel() {
    int i = blockIdx.x * blockDim.x + threadIdx.x;
    if (i < NN) g_cnt[i] = 0;
}
__global__ void cnt_accum_kernel(const int* __restrict__ ei) {
    int e = blockIdx.x * blockDim.x + threadIdx.x;
    if (e < NE) atomicAdd(&g_cnt[ei[NE + e]], 1);
}
__global__ void scan1_kernel() {      // 98 blocks x 1024
    __shared__ int s[1024];
    int t = threadIdx.x;
    int i = blockIdx.x * 1024 + t;
    int x = (i < NN) ? g_cnt[i] : 0;
    s[t] = x;
    __syncthreads();
    #pragma unroll
    for (int off = 1; off < 1024; off <<= 1) {
        int v = (t >= off) ? s[t - off] : 0;
        __syncthreads();
        s[t] += v;
        __syncthreads();
    }
    if (i < NN) g_rp[i] = s[t] - x;           // block-local exclusive
    if (t == 1023) g_bsum[blockIdx.x] = s[1023];
}
__global__ void scan2_kernel(int nblk) {      // 1 thread
    int run = 0;
    for (int b = 0; b < nblk; b++) { g_boff[b] = run; run += g_bsum[b]; }
}
__global__ void fin_kernel() {
    int i = blockIdx.x * blockDim.x + threadIdx.x;
    if (i >= NN) return;
    int rp = g_rp[i] + g_boff[i >> 10];
    g_rp[i] = rp;
    g_cur[i] = rp;
    g_deg[i] = rsqrtf(1.0f + (float)g_cnt[i]);
    if (i == 0) g_rp[NN] = NE;
}
__global__ void scatter_kernel(const int* __restrict__ ei) {
    int e = blockIdx.x * blockDim.x + threadIdx.x;
    if (e >= NE) return;
    int c = ei[NE + e];
    int slot = atomicAdd(&g_cur[c], 1);
    g_csr[slot] = ei[e];
}

// ---------------- aggregation: warp per node, CSR gather (no atomics) ------
__global__ void agg_kernel(const float* __restrict__ src) {
    int gid  = blockIdx.x * blockDim.x + threadIdx.x;
    int node = gid >> 5;
    if (node >= NN) return;
    int lane = gid & 31;
    const float4* s4 = (const float4*)src;
    float dn = g_deg[node];
    float4 acc = s4[(size_t)node * 32 + lane];
    float w0 = dn * dn;
    acc.x *= w0; acc.y *= w0; acc.z *= w0; acc.w *= w0;
    int j   = g_rp[node];
    int end = g_rp[node + 1];
    for (; j + 1 < end; j += 2) {
        int sa = g_csr[j], sb = g_csr[j + 1];
        float wa = dn * g_deg[sa], wb = dn * g_deg[sb];
        float4 va = s4[(size_t)sa * 32 + lane];
        float4 vb = s4[(size_t)sb * 32 + lane];
        acc.x += wa * va.x + wb * vb.x;
        acc.y += wa * va.y + wb * vb.y;
        acc.z += wa * va.z + wb * vb.z;
        acc.w += wa * va.w + wb * vb.w;
    }
    if (j < end) {
        int sa = g_csr[j];
        float wa = dn * g_deg[sa];
        float4 va = s4[(size_t)sa * 32 + lane];
        acc.x += wa * va.x; acc.y += wa * va.y;
        acc.z += wa * va.z; acc.w += wa * va.w;
    }
    ((float4*)g_agg)[(size_t)node * 32 + lane] = acc;
}

// ---------------- weight transpose + fp16 split ----------------
__global__ void prep_weights(const float* __restrict__ w1,
                             const float* __restrict__ cw,
                             const float* __restrict__ w2) {
    int i = blockIdx.x * blockDim.x + threadIdx.x;
    const int N1 = HD * DIN;
    const int N2 = 2 * HD * HD;
    const int N3 = DOUT * HD;
    if (i < N1) {
        int n = i / DIN, k = i % DIN;
        split_f16(w1[(size_t)k * HD + n], g_w1t_hi[i], g_w1t_lo[i]);
    } else if (i < N1 + N2) {
        int j = i - N1;
        int l = j / (HD * HD), r = j % (HD * HD);
        int n = r / HD, k = r % HD;
        split_f16(cw[(size_t)l * HD * HD + (size_t)k * HD + n], g_cwt_hi[j], g_cwt_lo[j]);
    } else if (i < N1 + N2 + N3) {
        int j = i - N1 - N2;
        int n = j / HD, k = j % HD;
        split_f16(w2[(size_t)k * DOUT + n], g_w2t_hi[j], g_w2t_lo[j]);
    }
}

// =================== mma.sync fp16x3 GEMM ===================
// C[M,BN] = opA[M,K] @ Bt[BN,K]^T, opA = (COMBINE ? ca*A + cb*A2 : A)
// Bt pre-split K-major fp16 (hi/lo). BM=128, BK=32, 8 warps.
template<int BN, bool RELU, bool BIAS, bool COMBINE>
__global__ void __launch_bounds__(256, 1)
mma_gemm(const float* __restrict__ A, const float* __restrict__ A2,
         const __half* __restrict__ Bhi, const __half* __restrict__ Blo,
         const float* __restrict__ bias, float* __restrict__ C,
         int M, int K, float ca, float cb)
{
    constexpr int BM = 128, BK = 32, BKP = 40;      // padded stride (halves, 80B)
    constexpr int MF = 4;
    constexpr int WN = BN / 4;
    constexpr int NF = WN / 8;                      // 4 (BN=128) or 2 (BN=64)
    constexpr int ASZ = BM * BKP;                   // halves per A buffer (5120)
    constexpr int BSZ = BN * BKP;
    constexpr int AB = ASZ * 2;                     // bytes
    constexpr int BB = BSZ * 2;

    extern __shared__ __half smh[];
    __half* AHp = smh;                 // [2][ASZ]
    __half* ALp = smh + 2 * ASZ;
    const uint32_t sb  = smem_to_u32(smh);
    const uint32_t uAH = sb;
    const uint32_t uAL = sb + 2 * AB;
    const uint32_t uBH = sb + 4 * AB;
    const uint32_t uBL = sb + 4 * AB + 2 * BB;

    const int tid  = threadIdx.x;
    const int lane = tid & 31;
    const int wid  = tid >> 5;
    const int wm   = (wid >> 2) * 64;
    const int wn   = (wid & 3) * WN;
    const int blockM = blockIdx.x * BM;

    // ldmatrix lane offsets
    const int a_r  = lane & 15, a_kc = lane >> 4;                 // A x4
    const int b_r  = (lane & 7) + ((lane >> 4) << 3);             // B x4
    const int b_kc = (lane >> 3) & 1;

    float acc[MF][NF][4];
    #pragma unroll
    for (int mf = 0; mf < MF; mf++)
        #pragma unroll
        for (int nf = 0; nf < NF; nf++)
            #pragma unroll
            for (int q = 0; q < 4; q++) acc[mf][nf][q] = 0.0f;

    const int nit = K / BK;

    auto fillB = [&](int i, int b) {
        constexpr int CH = BN * 4;              // 16B chunks per component
        #pragma unroll
        for (int it = 0; it < CH / 256; it++) {
            int id = tid + it * 256;
            int n  = id >> 2, c = id & 3;
            uint32_t off = (uint32_t)b * BB + (uint32_t)n * (BKP * 2) + c * 16;
            cp_async16(uBH + off, Bhi + (size_t)n * K + i * BK + c * 8);
            cp_async16(uBL + off, Blo + (size_t)n * K + i * BK + c * 8);
        }
    };
    float4 aR[4];
    auto loadA = [&](int i) {
        #pragma unroll
        for (int it = 0; it < 4; it++) {
            int id  = tid + it * 256;           // BM * 8 f4-chunks = 1024
            int row = id >> 3, c4 = id & 7;
            int gr  = blockM + row;
            float4 v = make_float4(0.f, 0.f, 0.f, 0.f);
            if (gr < M) {
                v = *(const float4*)(A + (size_t)gr * K + i * BK + c4 * 4);
                if (COMBINE) {
                    float4 u = *(const float4*)(A2 + (size_t)gr * K + i * BK + c4 * 4);
                    v.x = ca * v.x + cb * u.x;
                    v.y = ca * v.y + cb * u.y;
                    v.z = ca * v.z + cb * u.z;
                    v.w = ca * v.w + cb * u.w;
                }
            }
            aR[it] = v;
        }
    };
    auto storeA = [&](int b) {
        #pragma unroll
        for (int it = 0; it < 4; it++) {
            int id  = tid + it * 256;
            int row = id >> 3, c4 = id & 7;
            float4 v = aR[it];
            __half hx, lx, hy, ly, hz, lz, hw, lw;
            split_f16(v.x, hx, lx); split_f16(v.y, hy, ly);
            split_f16(v.z, hz, lz); split_f16(v.w, hw, lw);
            int off = b * ASZ + row * BKP + c4 * 4;
            ((half2*)(AHp + off))[0] = __halves2half2(hx, hy);
            ((half2*)(AHp + off))[1] = __halves2half2(hz, hw);
            ((half2*)(ALp + off))[0] = __halves2half2(lx, ly);
            ((half2*)(ALp + off))[1] = __halves2half2(lz, lw);
        }
    };
    auto compute = [&](int b) {
        #pragma unroll
        for (int ks = 0; ks < 2; ks++) {
            uint32_t ah[MF][4], al[MF][4];
            #pragma unroll
            for (int mf = 0; mf < MF; mf++) {
                uint32_t off = (uint32_t)(wm + mf * 16 + a_r) * (BKP * 2) + ks * 32 + a_kc * 16;
                ldsm4(ah[mf], uAH + (uint32_t)b * AB + off);
                ldsm4(al[mf], uAL + (uint32_t)b * AB + off);
            }
            uint32_t bh[NF][2], bl[NF][2];
            #pragma unroll
            for (int nb = 0; nb < NF / 2; nb++) {
                uint32_t off = (uint32_t)(wn + nb * 16 + b_r) * (BKP * 2) + ks * 32 + b_kc * 16;
                uint32_t t[4];
                ldsm4(t, uBH + (uint32_t)b * BB + off);
                bh[2 * nb][0] = t[0]; bh[2 * nb][1] = t[1];
                bh[2 * nb + 1][0] = t[2]; bh[2 * nb + 1][1] = t[3];
                ldsm4(t, uBL + (uint32_t)b * BB + off);
                bl[2 * nb][0] = t[0]; bl[2 * nb][1] = t[1];
                bl[2 * nb + 1][0] = t[2]; bl[2 * nb + 1][1] = t[3];
            }
            #pragma unroll
            for (int mf = 0; mf < MF; mf++)
                #pragma unroll
                for (int nf = 0; nf < NF; nf++) {
                    mma_f16(acc[mf][nf], ah[mf], bh[nf]);
                    mma_f16(acc[mf][nf], ah[mf], bl[nf]);
                    mma_f16(acc[mf][nf], al[mf], bh[nf]);
                }
        }
    };

    // prologue
    loadA(0);
    fillB(0, 0);
    cp_commit();
    storeA(0);

    for (int i = 0; i < nit; i++) {
        const int b = i & 1;
        if (i + 1 < nit) {
            loadA(i + 1);
            fillB(i + 1, b ^ 1);
            cp_commit();
            cp_wait<1>();
        } else {
            cp_wait<0>();
        }
        __syncthreads();
        compute(b);
        if (i + 1 < nit) storeA(b ^ 1);
    }

    // epilogue
    #pragma unroll
    for (int mf = 0; mf < MF; mf++) {
        int row0 = blockM + wm + mf * 16 + (lane >> 2);
        #pragma unroll
        for (int nf = 0; nf < NF; nf++) {
            int col = wn + nf * 8 + (lane & 3) * 2;
            float2 v0 = make_float2(acc[mf][nf][0], acc[mf][nf][1]);
            float2 v1 = make_float2(acc[mf][nf][2], acc[mf][nf][3]);
            if (BIAS) {
                float b0 = bias[col], b1 = bias[col + 1];
                v0.x += b0; v0.y += b1;
                v1.x += b0; v1.y += b1;
            }
            if (RELU) {
                v0.x = fmaxf(v0.x, 0.f); v0.y = fmaxf(v0.y, 0.f);
                v1.x = fmaxf(v1.x, 0.f); v1.y = fmaxf(v1.y, 0.f);
            }
            if (row0 < M)     *(float2*)(C + (size_t)row0 * BN + col)       = v0;
            if (row0 + 8 < M) *(float2*)(C + (size_t)(row0 + 8) * BN + col) = v1;
        }
    }
}

// ---------------- launch ----------------
extern "C" void kernel_launch(void* const* d_in, const int* in_sizes, int n_in,
                              void* d_out, int out_size)
{
    const float* x  = (const float*)d_in[0];
    const int*   ei = (const int*)  d_in[1];
    const float* w1 = (const float*)d_in[2];
    const float* b1 = (const float*)d_in[3];
    const float* cw = (const float*)d_in[4];
    const float* w2 = (const float*)d_in[5];
    const float* b2 = (const float*)d_in[6];

    float* out    = (float*)d_out;
    float* hout   = out;
    float* logits = out + (size_t)NN * HD;

    float *p_h0, *p_h, *p_agg;
    __half *p_w1h, *p_w1l, *p_cwh, *p_cwl, *p_w2h, *p_w2l;
    cudaGetSymbolAddress((void**)&p_h0,  g_h0);
    cudaGetSymbolAddress((void**)&p_h,   g_h);
    cudaGetSymbolAddress((void**)&p_agg, g_agg);
    cudaGetSymbolAddress((void**)&p_w1h, g_w1t_hi);
    cudaGetSymbolAddress((void**)&p_w1l, g_w1t_lo);
    cudaGetSymbolAddress((void**)&p_cwh, g_cwt_hi);
    cudaGetSymbolAddress((void**)&p_cwl, g_cwt_lo);
    cudaGetSymbolAddress((void**)&p_w2h, g_w2t_hi);
    cudaGetSymbolAddress((void**)&p_w2l, g_w2t_lo);

    const int TPB = 256;
    const int gemm_grid = (NN + 127) / 128;                    // 782
    const int NBLK = (NN + 1023) / 1024;                       // 98
    const int SMEM_128 = (4 * 128 * 40 + 4 * 128 * 40) * 2;    // 81920 B
    const int SMEM_64  = (4 * 128 * 40 + 4 * 64 * 40) * 2;     // 61440 B

    cudaFuncSetAttribute(mma_gemm<128, true,  true,  false>,
                         cudaFuncAttributeMaxDynamicSharedMemorySize, SMEM_128);
    cudaFuncSetAttribute(mma_gemm<128, false, false, true>,
                         cudaFuncAttributeMaxDynamicSharedMemorySize, SMEM_128);
    cudaFuncSetAttribute(mma_gemm<64,  false, true,  false>,
                         cudaFuncAttributeMaxDynamicSharedMemorySize, SMEM_64);

    // CSR build + dinv + weight prep
    cnt_init_kernel <<<(NN + TPB - 1) / TPB, TPB>>>();
    cnt_accum_kernel<<<(NE + TPB - 1) / TPB, TPB>>>(ei);
    scan1_kernel    <<<NBLK, 1024>>>();
    scan2_kernel    <<<1, 1>>>(NBLK);
    fin_kernel      <<<(NN + TPB - 1) / TPB, TPB>>>();
    scatter_kernel  <<<(NE + TPB - 1) / TPB, TPB>>>(ei);
    prep_weights    <<<(HD*DIN + 2*HD*HD + DOUT*HD + TPB - 1) / TPB, TPB>>>(w1, cw, w2);

    // h0 = relu(x @ w1 + b1)
    mma_gemm<128, true, true, false><<<gemm_grid, 256, SMEM_128>>>(
        x, nullptr, p_w1h, p_w1l, b1, p_h0, NN, DIN, 0.f, 0.f);

    // ---- layer 1 ----
    agg_kernel<<<(NN * 32 + TPB - 1) / TPB, TPB>>>(p_h0);
    mma_gemm<128, false, false, true><<<gemm_grid, 256, SMEM_128>>>(
        p_agg, p_h0, p_cwh, p_cwl, nullptr, p_h, NN, HD, 0.9f, 0.1f);

    // ---- layer 2 (writes h directly to d_out) ----
    agg_kernel<<<(NN * 32 + TPB - 1) / TPB, TPB>>>(p_h);
    mma_gemm<128, false, false, true><<<gemm_grid, 256, SMEM_128>>>(
        p_agg, p_h0, p_cwh + HD * HD, p_cwl + HD * HD, nullptr, hout, NN, HD, 0.9f, 0.1f);

    // logits = hout @ w2 + b2
    mma_gemm<64, false, true, false><<<gemm_grid, 256, SMEM_64>>>(
        hout, nullptr, p_w2h, p_w2l, b2, logits, NN, HD, 0.f, 0.f);
}

// round 8
// speedup vs baseline: 2.2939x; 1.2025x over previous
#include <cuda_runtime.h>
#include <cuda_fp16.h>
#include <cstdint>

#define NN   100000
#define NE   1600000
#define DIN  512
#define HD   128
#define DOUT 64

// ---------------- scratch (device globals: allocation-free) ----------------
__device__ float g_deg[NN];                     // dinv
__device__ float g_h0 [(size_t)NN * HD];
__device__ float g_h  [(size_t)NN * HD];
__device__ float g_agg[(size_t)NN * HD];
// CSR build
__device__ int g_cnt[NN];
__device__ int g_rp [NN + 1];
__device__ int g_cur[NN];
__device__ int g_csr[NE];
__device__ int g_bsum[128], g_boff[128];
// K-major, fp16-split weights: [N][K]
__device__ __half g_w1t_hi[HD * DIN],    g_w1t_lo[HD * DIN];
__device__ __half g_cwt_hi[2 * HD * HD], g_cwt_lo[2 * HD * HD];
__device__ __half g_w2t_hi[DOUT * HD],   g_w2t_lo[DOUT * HD];

// ======================= helpers =====================
__device__ __forceinline__ uint32_t smem_to_u32(const void* p) {
    uint32_t a;
    asm("{ .reg .u64 t; cvta.to.shared.u64 t, %1; cvt.u32.u64 %0, t; }" : "=r"(a) : "l"(p));
    return a;
}
__device__ __forceinline__ void ldsm4(uint32_t* r, uint32_t addr) {
    asm volatile("ldmatrix.sync.aligned.m8n8.x4.shared.b16 {%0,%1,%2,%3}, [%4];"
                 : "=r"(r[0]), "=r"(r[1]), "=r"(r[2]), "=r"(r[3]) : "r"(addr));
}
__device__ __forceinline__ void mma_f16(float* c, const uint32_t* a, const uint32_t* b) {
    asm volatile("mma.sync.aligned.m16n8k16.row.col.f32.f16.f16.f32 "
                 "{%0,%1,%2,%3}, {%4,%5,%6,%7}, {%8,%9}, {%0,%1,%2,%3};"
                 : "+f"(c[0]), "+f"(c[1]), "+f"(c[2]), "+f"(c[3])
                 : "r"(a[0]), "r"(a[1]), "r"(a[2]), "r"(a[3]), "r"(b[0]), "r"(b[1]));
}
__device__ __forceinline__ void cp_async16(uint32_t dst, const void* src) {
    asm volatile("cp.async.cg.shared.global [%0], [%1], 16;"
                 :: "r"(dst), "l"((unsigned long long)__cvta_generic_to_global(src)) : "memory");
}
__device__ __forceinline__ void cp_commit() {
    asm volatile("cp.async.commit_group;" ::: "memory");
}
template<int N> __device__ __forceinline__ void cp_wait() {
    asm volatile("cp.async.wait_group %0;" :: "n"(N) : "memory");
}
__device__ __forceinline__ void split_f16(float x, __half& hi, __half& lo) {
    hi = __float2half_rn(x);
    lo = __float2half_rn(x - __half2float(hi));
}

// ---------------- CSR build ----------------
__global__ void cnt_init_kernel() {
    int i = blockIdx.x * blockDim.x + threadIdx.x;
    if (i < NN) g_cnt[i] = 0;
}
__global__ void cnt_accum_kernel(const int* __restrict__ ei) {
    int e = blockIdx.x * blockDim.x + threadIdx.x;
    if (e < NE) atomicAdd(&g_cnt[ei[NE + e]], 1);
}
__global__ void scan1_kernel() {      // 98 blocks x 1024
    __shared__ int s[1024];
    int t = threadIdx.x;
    int i = blockIdx.x * 1024 + t;
    int x = (i < NN) ? g_cnt[i] : 0;
    s[t] = x;
    __syncthreads();
    #pragma unroll
    for (int off = 1; off < 1024; off <<= 1) {
        int v = (t >= off) ? s[t - off] : 0;
        __syncthreads();
        s[t] += v;
        __syncthreads();
    }
    if (i < NN) g_rp[i] = s[t] - x;           // block-local exclusive
    if (t == 1023) g_bsum[blockIdx.x] = s[1023];
}
__global__ void scan2_kernel(int nblk) {      // 1 block x 128, parallel scan
    __shared__ int s[128];
    int t = threadIdx.x;
    int v = (t < nblk) ? g_bsum[t] : 0;
    s[t] = v;
    __syncthreads();
    #pragma unroll
    for (int off = 1; off < 128; off <<= 1) {
        int u = (t >= off) ? s[t - off] : 0;
        __syncthreads();
        s[t] += u;
        __syncthreads();
    }
    if (t < nblk) g_boff[t] = s[t] - v;       // exclusive
}
__global__ void fin_kernel() {
    int i = blockIdx.x * blockDim.x + threadIdx.x;
    if (i >= NN) return;
    int rp = g_rp[i] + g_boff[i >> 10];
    g_rp[i] = rp;
    g_cur[i] = rp;
    g_deg[i] = rsqrtf(1.0f + (float)g_cnt[i]);
    if (i == 0) g_rp[NN] = NE;
}
__global__ void scatter_kernel(const int* __restrict__ ei) {
    int e = blockIdx.x * blockDim.x + threadIdx.x;
    if (e >= NE) return;
    int c = ei[NE + e];
    int slot = atomicAdd(&g_cur[c], 1);
    g_csr[slot] = ei[e];
}

// ---------------- aggregation: warp per node, CSR gather, MLP=4 ------------
__global__ void agg_kernel(const float* __restrict__ src) {
    int gid  = blockIdx.x * blockDim.x + threadIdx.x;
    int node = gid >> 5;
    if (node >= NN) return;
    int lane = gid & 31;
    const float4* s4 = (const float4*)src;
    float dn = g_deg[node];
    float4 acc = s4[(size_t)node * 32 + lane];
    float w0 = dn * dn;
    acc.x *= w0; acc.y *= w0; acc.z *= w0; acc.w *= w0;
    int j   = g_rp[node];
    int end = g_rp[node + 1];
    for (; j + 3 < end; j += 4) {
        int s0 = g_csr[j],     s1 = g_csr[j + 1];
        int s2 = g_csr[j + 2], s3 = g_csr[j + 3];
        float q0 = dn * g_deg[s0], q1 = dn * g_deg[s1];
        float q2 = dn * g_deg[s2], q3 = dn * g_deg[s3];
        float4 v0 = s4[(size_t)s0 * 32 + lane];
        float4 v1 = s4[(size_t)s1 * 32 + lane];
        float4 v2 = s4[(size_t)s2 * 32 + lane];
        float4 v3 = s4[(size_t)s3 * 32 + lane];
        acc.x += q0 * v0.x + q1 * v1.x + q2 * v2.x + q3 * v3.x;
        acc.y += q0 * v0.y + q1 * v1.y + q2 * v2.y + q3 * v3.y;
        acc.z += q0 * v0.z + q1 * v1.z + q2 * v2.z + q3 * v3.z;
        acc.w += q0 * v0.w + q1 * v1.w + q2 * v2.w + q3 * v3.w;
    }
    for (; j < end; j++) {
        int sa = g_csr[j];
        float wa = dn * g_deg[sa];
        float4 va = s4[(size_t)sa * 32 + lane];
        acc.x += wa * va.x; acc.y += wa * va.y;
        acc.z += wa * va.z; acc.w += wa * va.w;
    }
    ((float4*)g_agg)[(size_t)node * 32 + lane] = acc;
}

// ---------------- weight transpose + fp16 split ----------------
__global__ void prep_weights(const float* __restrict__ w1,
                             const float* __restrict__ cw,
                             const float* __restrict__ w2) {
    int i = blockIdx.x * blockDim.x + threadIdx.x;
    const int N1 = HD * DIN;
    const int N2 = 2 * HD * HD;
    const int N3 = DOUT * HD;
    if (i < N1) {
        int n = i / DIN, k = i % DIN;
        split_f16(w1[(size_t)k * HD + n], g_w1t_hi[i], g_w1t_lo[i]);
    } else if (i < N1 + N2) {
        int j = i - N1;
        int l = j / (HD * HD), r = j % (HD * HD);
        int n = r / HD, k = r % HD;
        split_f16(cw[(size_t)l * HD * HD + (size_t)k * HD + n], g_cwt_hi[j], g_cwt_lo[j]);
    } else if (i < N1 + N2 + N3) {
        int j = i - N1 - N2;
        int n = j / HD, k = j % HD;
        split_f16(w2[(size_t)k * DOUT + n], g_w2t_hi[j], g_w2t_lo[j]);
    }
}

// =================== mma.sync fp16x3 GEMM, BK=16, 2 CTAs/SM ===================
// C[M,BN] = opA[M,K] @ Bt[BN,K]^T, opA = (COMBINE ? ca*A + cb*A2 : A)
// RACE-FIXED pipeline: prefetch into a buffer only AFTER the barrier that
// proves the previous iteration's readers of that buffer are done.
template<int BN, bool RELU, bool BIAS, bool COMBINE>
__global__ void __launch_bounds__(256, 2)
mma_gemm(const float* __restrict__ A, const float* __restrict__ A2,
         const __half* __restrict__ Bhi, const __half* __restrict__ Blo,
         const float* __restrict__ bias, float* __restrict__ C,
         int M, int K, float ca, float cb)
{
    constexpr int BM = 128, BK = 16, BKP = 24;      // padded stride (48 B)
    constexpr int MF = 4;
    constexpr int WN = BN / 4;
    constexpr int NF = WN / 8;                      // 4 (BN=128) or 2 (BN=64)
    constexpr int ASZ = BM * BKP;                   // halves (3072)
    constexpr int BSZ = BN * BKP;
    constexpr int AB = ASZ * 2;                     // bytes (6144)
    constexpr int BB = BSZ * 2;

    extern __shared__ __half smh[];
    __half* AHp = smh;                 // [2][ASZ]
    __half* ALp = smh + 2 * ASZ;
    const uint32_t sb  = smem_to_u32(smh);
    const uint32_t uAH = sb;
    const uint32_t uAL = sb + 2 * AB;
    const uint32_t uBH = sb + 4 * AB;
    const uint32_t uBL = sb + 4 * AB + 2 * BB;

    const int tid  = threadIdx.x;
    const int lane = tid & 31;
    const int wid  = tid >> 5;
    const int wm   = (wid >> 2) * 64;
    const int wn   = (wid & 3) * WN;
    const int blockM = blockIdx.x * BM;

    // ldmatrix lane offsets
    const int a_r  = lane & 15, a_kc = lane >> 4;                 // A x4
    const int b_r  = (lane & 7) + ((lane >> 4) << 3);             // B x4
    const int b_kc = (lane >> 3) & 1;

    float acc[MF][NF][4];
    #pragma unroll
    for (int mf = 0; mf < MF; mf++)
        #pragma unroll
        for (int nf = 0; nf < NF; nf++)
            #pragma unroll
            for (int q = 0; q < 4; q++) acc[mf][nf][q] = 0.0f;

    const int nit = K / BK;

    auto fillB = [&](int i, int b) {
        constexpr int CH = BN * 2;          // 16B chunks per component
        #pragma unroll
        for (int it = 0; it < (CH + 255) / 256; it++) {
            int id = tid + it * 256;
            if (CH % 256 == 0 || id < CH) {
                int n = id >> 1, c = id & 1;
                uint32_t off = (uint32_t)b * BB + (uint32_t)n * (BKP * 2) + c * 16;
                cp_async16(uBH + off, Bhi + (size_t)n * K + i * BK + c * 8);
                cp_async16(uBL + off, Blo + (size_t)n * K + i * BK + c * 8);
            }
        }
    };
    float4 aR[2];
    auto loadA = [&](int i) {
        #pragma unroll
        for (int it = 0; it < 2; it++) {
            int id  = tid + it * 256;           // BM*4 f4-chunks = 512
            int row = id >> 2, c4 = id & 3;
            int gr  = blockM + row;
            float4 v = make_float4(0.f, 0.f, 0.f, 0.f);
            if (gr < M) {
                v = *(const float4*)(A + (size_t)gr * K + i * BK + c4 * 4);
                if (COMBINE) {
                    float4 u = *(const float4*)(A2 + (size_t)gr * K + i * BK + c4 * 4);
                    v.x = ca * v.x + cb * u.x;
                    v.y = ca * v.y + cb * u.y;
                    v.z = ca * v.z + cb * u.z;
                    v.w = ca * v.w + cb * u.w;
                }
            }
            aR[it] = v;
        }
    };
    auto storeA = [&](int b) {
        #pragma unroll
        for (int it = 0; it < 2; it++) {
            int id  = tid + it * 256;
            int row = id >> 2, c4 = id & 3;
            float4 v = aR[it];
            __half hx, lx, hy, ly, hz, lz, hw, lw;
            split_f16(v.x, hx, lx); split_f16(v.y, hy, ly);
            split_f16(v.z, hz, lz); split_f16(v.w, hw, lw);
            int off = b * ASZ + row * BKP + c4 * 4;
            ((half2*)(AHp + off))[0] = __halves2half2(hx, hy);
            ((half2*)(AHp + off))[1] = __halves2half2(hz, hw);
            ((half2*)(ALp + off))[0] = __halves2half2(lx, ly);
            ((half2*)(ALp + off))[1] = __halves2half2(lz, lw);
        }
    };
    auto compute = [&](int b) {
        uint32_t ah[MF][4], al[MF][4];
        #pragma unroll
        for (int mf = 0; mf < MF; mf++) {
            uint32_t off = (uint32_t)(wm + mf * 16 + a_r) * (BKP * 2) + a_kc * 16;
            ldsm4(ah[mf], uAH + (uint32_t)b * AB + off);
            ldsm4(al[mf], uAL + (uint32_t)b * AB + off);
        }
        uint32_t bh[NF][2], bl[NF][2];
        #pragma unroll
        for (int nb = 0; nb < NF / 2; nb++) {
            uint32_t off = (uint32_t)(wn + nb * 16 + b_r) * (BKP * 2) + b_kc * 16;
            uint32_t t[4];
            ldsm4(t, uBH + (uint32_t)b * BB + off);
            bh[2 * nb][0] = t[0]; bh[2 * nb][1] = t[1];
            bh[2 * nb + 1][0] = t[2]; bh[2 * nb + 1][1] = t[3];
            ldsm4(t, uBL + (uint32_t)b * BB + off);
            bl[2 * nb][0] = t[0]; bl[2 * nb][1] = t[1];
            bl[2 * nb + 1][0] = t[2]; bl[2 * nb + 1][1] = t[3];
        }
        #pragma unroll
        for (int mf = 0; mf < MF; mf++)
            #pragma unroll
            for (int nf = 0; nf < NF; nf++) {
                mma_f16(acc[mf][nf], ah[mf], bh[nf]);
                mma_f16(acc[mf][nf], ah[mf], bl[nf]);
                mma_f16(acc[mf][nf], al[mf], bh[nf]);
            }
    };

    // ---- prologue: tile 0 ----
    loadA(0);
    storeA(0);          // A buf 0 written before first barrier
    fillB(0, 0);
    cp_commit();

    // ---- mainloop (race-free ordering) ----
    for (int i = 0; i < nit; i++) {
        const int b = i & 1;
        cp_wait<0>();           // B tile i landed
        __syncthreads();        // + all warps done with iteration i-1 (buffers b^1 free)
        if (i + 1 < nit) {
            fillB(i + 1, b ^ 1);    // prefetch into freed buffer, overlaps compute(b)
            cp_commit();
            loadA(i + 1);
        }
        compute(b);
        if (i + 1 < nit) storeA(b ^ 1);   // safe: iter i-1 readers of b^1 proven done
    }

    // ---- epilogue ----
    #pragma unroll
    for (int mf = 0; mf < MF; mf++) {
        int row0 = blockM + wm + mf * 16 + (lane >> 2);
        #pragma unroll
        for (int nf = 0; nf < NF; nf++) {
            int col = wn + nf * 8 + (lane & 3) * 2;
            float2 v0 = make_float2(acc[mf][nf][0], acc[mf][nf][1]);
            float2 v1 = make_float2(acc[mf][nf][2], acc[mf][nf][3]);
            if (BIAS) {
                float b0 = bias[col], b1 = bias[col + 1];
                v0.x += b0; v0.y += b1;
                v1.x += b0; v1.y += b1;
            }
            if (RELU) {
                v0.x = fmaxf(v0.x, 0.f); v0.y = fmaxf(v0.y, 0.f);
                v1.x = fmaxf(v1.x, 0.f); v1.y = fmaxf(v1.y, 0.f);
            }
            if (row0 < M)     *(float2*)(C + (size_t)row0 * BN + col)       = v0;
            if (row0 + 8 < M) *(float2*)(C + (size_t)(row0 + 8) * BN + col) = v1;
        }
    }
}

// ---------------- launch ----------------
extern "C" void kernel_launch(void* const* d_in, const int* in_sizes, int n_in,
                              void* d_out, int out_size)
{
    const float* x  = (const float*)d_in[0];
    const int*   ei = (const int*)  d_in[1];
    const float* w1 = (const float*)d_in[2];
    const float* b1 = (const float*)d_in[3];
    const float* cw = (const float*)d_in[4];
    const float* w2 = (const float*)d_in[5];
    const float* b2 = (const float*)d_in[6];

    float* out    = (float*)d_out;
    float* hout   = out;
    float* logits = out + (size_t)NN * HD;

    float *p_h0, *p_h, *p_agg;
    __half *p_w1h, *p_w1l, *p_cwh, *p_cwl, *p_w2h, *p_w2l;
    cudaGetSymbolAddress((void**)&p_h0,  g_h0);
    cudaGetSymbolAddress((void**)&p_h,   g_h);
    cudaGetSymbolAddress((void**)&p_agg, g_agg);
    cudaGetSymbolAddress((void**)&p_w1h, g_w1t_hi);
    cudaGetSymbolAddress((void**)&p_w1l, g_w1t_lo);
    cudaGetSymbolAddress((void**)&p_cwh, g_cwt_hi);
    cudaGetSymbolAddress((void**)&p_cwl, g_cwt_lo);
    cudaGetSymbolAddress((void**)&p_w2h, g_w2t_hi);
    cudaGetSymbolAddress((void**)&p_w2l, g_w2t_lo);

    const int TPB = 256;
    const int gemm_grid = (NN + 127) / 128;                    // 782
    const int NBLK = (NN + 1023) / 1024;                       // 98
    const int SMEM_128 = (4 * 128 * 24 + 4 * 128 * 24) * 2;    // 49152 B
    const int SMEM_64  = (4 * 128 * 24 + 4 * 64 * 24) * 2;     // 36864 B

    cudaFuncSetAttribute(mma_gemm<128, true,  true,  false>,
                         cudaFuncAttributeMaxDynamicSharedMemorySize, SMEM_128);
    cudaFuncSetAttribute(mma_gemm<128, false, false, true>,
                         cudaFuncAttributeMaxDynamicSharedMemorySize, SMEM_128);
    cudaFuncSetAttribute(mma_gemm<64,  false, true,  false>,
                         cudaFuncAttributeMaxDynamicSharedMemorySize, SMEM_64);

    // launches 1-3, then gemm1 as the 4th launch (profiler capture slot)
    cnt_init_kernel <<<(NN + TPB - 1) / TPB, TPB>>>();
    cnt_accum_kernel<<<(NE + TPB - 1) / TPB, TPB>>>(ei);
    prep_weights    <<<(HD*DIN + 2*HD*HD + DOUT*HD + TPB - 1) / TPB, TPB>>>(w1, cw, w2);

    // h0 = relu(x @ w1 + b1)   [launch #4 -> profiled]
    mma_gemm<128, true, true, false><<<gemm_grid, 256, SMEM_128>>>(
        x, nullptr, p_w1h, p_w1l, b1, p_h0, NN, DIN, 0.f, 0.f);

    // rest of CSR build (independent of gemm1, stream-ordered after)
    scan1_kernel    <<<NBLK, 1024>>>();
    scan2_kernel    <<<1, 128>>>(NBLK);
    fin_kernel      <<<(NN + TPB - 1) / TPB, TPB>>>();
    scatter_kernel  <<<(NE + TPB - 1) / TPB, TPB>>>(ei);

    // ---- layer 1 ----
    agg_kernel<<<(NN * 32 + TPB - 1) / TPB, TPB>>>(p_h0);
    mma_gemm<128, false, false, true><<<gemm_grid, 256, SMEM_128>>>(
        p_agg, p_h0, p_cwh, p_cwl, nullptr, p_h, NN, HD, 0.9f, 0.1f);

    // ---- layer 2 (writes h directly to d_out) ----
    agg_kernel<<<(NN * 32 + TPB - 1) / TPB, TPB>>>(p_h);
    mma_gemm<128, false, false, true><<<gemm_grid, 256, SMEM_128>>>(
        p_agg, p_h0, p_cwh + HD * HD, p_cwl + HD * HD, nullptr, hout, NN, HD, 0.9f, 0.1f);

    // logits = hout @ w2 + b2
    mma_gemm<64, false, true, false><<<gemm_grid, 256, SMEM_64>>>(
        hout, nullptr, p_w2h, p_w2l, b2, logits, NN, HD, 0.f, 0.f);
}

// round 10
// speedup vs baseline: 2.6100x; 1.1378x over previous
#include <cuda_runtime.h>
#include <cuda_fp16.h>
#include <cstdint>

#define NN   100000
#define NE   1600000
#define DIN  512
#define HD   128
#define DOUT 64

// ---------------- scratch (device globals: allocation-free) ----------------
__device__ float g_deg[NN];                     // dinv
__device__ float g_h0 [(size_t)NN * HD];
__device__ float g_h  [(size_t)NN * HD];
// combined residual input for conv GEMMs, pre-split fp16
__device__ __half g_comb_hi[(size_t)NN * HD];
__device__ __half g_comb_lo[(size_t)NN * HD];
// CSR build
__device__ int g_cnt[NN];
__device__ int g_rp [NN + 1];
__device__ int g_cur[NN];
__device__ int g_csr[NE];
__device__ int g_bsum[128], g_boff[128];
// K-major, fp16-split weights: [N][K]
__device__ __half g_w1t_hi[HD * DIN],    g_w1t_lo[HD * DIN];
__device__ __half g_cwt_hi[2 * HD * HD], g_cwt_lo[2 * HD * HD];
__device__ __half g_w2t_hi[DOUT * HD],   g_w2t_lo[DOUT * HD];

// ======================= helpers =====================
__device__ __forceinline__ uint32_t smem_to_u32(const void* p) {
    uint32_t a;
    asm("{ .reg .u64 t; cvta.to.shared.u64 t, %1; cvt.u32.u64 %0, t; }" : "=r"(a) : "l"(p));
    return a;
}
__device__ __forceinline__ void ldsm4(uint32_t* r, uint32_t addr) {
    asm volatile("ldmatrix.sync.aligned.m8n8.x4.shared.b16 {%0,%1,%2,%3}, [%4];"
                 : "=r"(r[0]), "=r"(r[1]), "=r"(r[2]), "=r"(r[3]) : "r"(addr));
}
__device__ __forceinline__ void mma_f16(float* c, const uint32_t* a, const uint32_t* b) {
    asm volatile("mma.sync.aligned.m16n8k16.row.col.f32.f16.f16.f32 "
                 "{%0,%1,%2,%3}, {%4,%5,%6,%7}, {%8,%9}, {%0,%1,%2,%3};"
                 : "+f"(c[0]), "+f"(c[1]), "+f"(c[2]), "+f"(c[3])
                 : "r"(a[0]), "r"(a[1]), "r"(a[2]), "r"(a[3]), "r"(b[0]), "r"(b[1]));
}
__device__ __forceinline__ void cp_async16(uint32_t dst, const void* src) {
    asm volatile("cp.async.cg.shared.global [%0], [%1], 16;"
                 :: "r"(dst), "l"((unsigned long long)__cvta_generic_to_global(src)) : "memory");
}
__device__ __forceinline__ void cp_commit() {
    asm volatile("cp.async.commit_group;" ::: "memory");
}
template<int N> __device__ __forceinline__ void cp_wait() {
    asm volatile("cp.async.wait_group %0;" :: "n"(N) : "memory");
}
__device__ __forceinline__ void split_f16(float x, __half& hi, __half& lo) {
    hi = __float2half_rn(x);
    lo = __float2half_rn(x - __half2float(hi));
}

// ---------------- CSR build ----------------
__global__ void cnt_init_kernel() {
    int i = blockIdx.x * blockDim.x + threadIdx.x;
    if (i < NN) g_cnt[i] = 0;
}
__global__ void cnt_accum_kernel(const int* __restrict__ ei) {
    int e = blockIdx.x * blockDim.x + threadIdx.x;
    if (e < NE) atomicAdd(&g_cnt[ei[NE + e]], 1);
}
__global__ void scan1_kernel() {      // 98 blocks x 1024
    __shared__ int s[1024];
    int t = threadIdx.x;
    int i = blockIdx.x * 1024 + t;
    int x = (i < NN) ? g_cnt[i] : 0;
    s[t] = x;
    __syncthreads();
    #pragma unroll
    for (int off = 1; off < 1024; off <<= 1) {
        int v = (t >= off) ? s[t - off] : 0;
        __syncthreads();
        s[t] += v;
        __syncthreads();
    }
    if (i < NN) g_rp[i] = s[t] - x;           // block-local exclusive
    if (t == 1023) g_bsum[blockIdx.x] = s[1023];
}
__global__ void scan2_kernel(int nblk) {      // 1 block x 128, parallel scan
    __shared__ int s[128];
    int t = threadIdx.x;
    int v = (t < nblk) ? g_bsum[t] : 0;
    s[t] = v;
    __syncthreads();
    #pragma unroll
    for (int off = 1; off < 128; off <<= 1) {
        int u = (t >= off) ? s[t - off] : 0;
        __syncthreads();
        s[t] += u;
        __syncthreads();
    }
    if (t < nblk) g_boff[t] = s[t] - v;       // exclusive
}
__global__ void fin_kernel() {
    int i = blockIdx.x * blockDim.x + threadIdx.x;
    if (i >= NN) return;
    int rp = g_rp[i] + g_boff[i >> 10];
    g_rp[i] = rp;
    g_cur[i] = rp;
    g_deg[i] = rsqrtf(1.0f + (float)g_cnt[i]);
    if (i == 0) g_rp[NN] = NE;
}
__global__ void scatter_kernel(const int* __restrict__ ei) {
    int e = blockIdx.x * blockDim.x + threadIdx.x;
    if (e >= NE) return;
    int c = ei[NE + e];
    int slot = atomicAdd(&g_cur[c], 1);
    g_csr[slot] = ei[e];
}

// ------- aggregation + residual combine + fp16 split, warp per node --------
// comb = 0.9 * (sum_j norm_j * src[j] + dinv^2 * src[node]) + 0.1 * h0[node]
__global__ void agg_kernel(const float* __restrict__ src) {
    int gid  = blockIdx.x * blockDim.x + threadIdx.x;
    int node = gid >> 5;
    if (node >= NN) return;
    int lane = gid & 31;
    const float4* s4 = (const float4*)src;
    float dn = g_deg[node];
    float4 acc = s4[(size_t)node * 32 + lane];
    float w0 = dn * dn;
    acc.x *= w0; acc.y *= w0; acc.z *= w0; acc.w *= w0;
    int j   = g_rp[node];
    int end = g_rp[node + 1];
    for (; j + 3 < end; j += 4) {
        int s0 = g_csr[j],     s1 = g_csr[j + 1];
        int s2 = g_csr[j + 2], s3 = g_csr[j + 3];
        float q0 = dn * g_deg[s0], q1 = dn * g_deg[s1];
        float q2 = dn * g_deg[s2], q3 = dn * g_deg[s3];
        float4 v0 = s4[(size_t)s0 * 32 + lane];
        float4 v1 = s4[(size_t)s1 * 32 + lane];
        float4 v2 = s4[(size_t)s2 * 32 + lane];
        float4 v3 = s4[(size_t)s3 * 32 + lane];
        acc.x += q0 * v0.x + q1 * v1.x + q2 * v2.x + q3 * v3.x;
        acc.y += q0 * v0.y + q1 * v1.y + q2 * v2.y + q3 * v3.y;
        acc.z += q0 * v0.z + q1 * v1.z + q2 * v2.z + q3 * v3.z;
        acc.w += q0 * v0.w + q1 * v1.w + q2 * v2.w + q3 * v3.w;
    }
    for (; j < end; j++) {
        int sa = g_csr[j];
        float wa = dn * g_deg[sa];
        float4 va = s4[(size_t)sa * 32 + lane];
        acc.x += wa * va.x; acc.y += wa * va.y;
        acc.z += wa * va.z; acc.w += wa * va.w;
    }
    // residual combine + split
    float4 h0v = ((const float4*)g_h0)[(size_t)node * 32 + lane];
    float cx = 0.9f * acc.x + 0.1f * h0v.x;
    float cy = 0.9f * acc.y + 0.1f * h0v.y;
    float cz = 0.9f * acc.z + 0.1f * h0v.z;
    float cw = 0.9f * acc.w + 0.1f * h0v.w;
    __half hx, lx, hy, ly, hz, lz, hw, lw;
    split_f16(cx, hx, lx); split_f16(cy, hy, ly);
    split_f16(cz, hz, lz); split_f16(cw, hw, lw);
    half2* ph = (half2*)(g_comb_hi + (size_t)node * HD) + lane * 2;
    half2* pl = (half2*)(g_comb_lo + (size_t)node * HD) + lane * 2;
    ph[0] = __halves2half2(hx, hy); ph[1] = __halves2half2(hz, hw);
    pl[0] = __halves2half2(lx, ly); pl[1] = __halves2half2(lz, lw);
}

// ---------------- weight transpose + fp16 split ----------------
__global__ void prep_weights(const float* __restrict__ w1,
                             const float* __restrict__ cw,
                             const float* __restrict__ w2) {
    int i = blockIdx.x * blockDim.x + threadIdx.x;
    const int N1 = HD * DIN;
    const int N2 = 2 * HD * HD;
    const int N3 = DOUT * HD;
    if (i < N1) {
        int n = i / DIN, k = i % DIN;
        split_f16(w1[(size_t)k * HD + n], g_w1t_hi[i], g_w1t_lo[i]);
    } else if (i < N1 + N2) {
        int j = i - N1;
        int l = j / (HD * HD), r = j % (HD * HD);
        int n = r / HD, k = r % HD;
        split_f16(cw[(size_t)l * HD * HD + (size_t)k * HD + n], g_cwt_hi[j], g_cwt_lo[j]);
    } else if (i < N1 + N2 + N3) {
        int j = i - N1 - N2;
        int n = j / HD, k = j % HD;
        split_f16(w2[(size_t)k * DOUT + n], g_w2t_hi[j], g_w2t_lo[j]);
    }
}

// ======== shared GEMM compute core (BM=128, BK=32, 8 warps) ========
// smem layout bytes: AH | AL | BH | BL, each [2 bufs][rows][BKP=40 halves]
#define BKP 40
#define AB_BYTES (128 * BKP * 2)

template<int BN, int NF>
__device__ __forceinline__ void gemm_compute(
    uint32_t uAH, uint32_t uAL, uint32_t uBH, uint32_t uBL,
    int b, int wm, int wn, int a_r, int a_kc, int b_r, int b_kc,
    float (*acc)[NF][4])
{
    constexpr int BB = BN * BKP * 2;
    #pragma unroll
    for (int ks = 0; ks < 2; ks++) {
        uint32_t ah[4][4], al[4][4];
        #pragma unroll
        for (int mf = 0; mf < 4; mf++) {
            uint32_t off = (uint32_t)(wm + mf * 16 + a_r) * (BKP * 2) + ks * 32 + a_kc * 16;
            ldsm4(ah[mf], uAH + (uint32_t)b * AB_BYTES + off);
            ldsm4(al[mf], uAL + (uint32_t)b * AB_BYTES + off);
        }
        uint32_t bh[NF][2], bl[NF][2];
        #pragma unroll
        for (int nb = 0; nb < NF / 2; nb++) {
            uint32_t off = (uint32_t)(wn + nb * 16 + b_r) * (BKP * 2) + ks * 32 + b_kc * 16;
            uint32_t t[4];
            ldsm4(t, uBH + (uint32_t)b * BB + off);
            bh[2 * nb][0] = t[0]; bh[2 * nb][1] = t[1];
            bh[2 * nb + 1][0] = t[2]; bh[2 * nb + 1][1] = t[3];
            ldsm4(t, uBL + (uint32_t)b * BB + off);
            bl[2 * nb][0] = t[0]; bl[2 * nb][1] = t[1];
            bl[2 * nb + 1][0] = t[2]; bl[2 * nb + 1][1] = t[3];
        }
        #pragma unroll
        for (int mf = 0; mf < 4; mf++)
            #pragma unroll
            for (int nf = 0; nf < NF; nf++) {
                mma_f16(acc[mf][nf], ah[mf], bh[nf]);
                mma_f16(acc[mf][nf], ah[mf], bl[nf]);
                mma_f16(acc[mf][nf], al[mf], bh[nf]);
            }
    }
}

template<int BN, int NF, bool RELU, bool BIAS>
__device__ __forceinline__ void gemm_epilogue(
    float (*acc)[NF][4], const float* bias, float* C,
    int M, int blockM, int wm, int wn, int lane)
{
    #pragma unroll
    for (int mf = 0; mf < 4; mf++) {
        int row0 = blockM + wm + mf * 16 + (lane >> 2);
        #pragma unroll
        for (int nf = 0; nf < NF; nf++) {
            int col = wn + nf * 8 + (lane & 3) * 2;
            float2 v0 = make_float2(acc[mf][nf][0], acc[mf][nf][1]);
            float2 v1 = make_float2(acc[mf][nf][2], acc[mf][nf][3]);
            if (BIAS) {
                float b0 = bias[col], b1 = bias[col + 1];
                v0.x += b0; v0.y += b1;
                v1.x += b0; v1.y += b1;
            }
            if (RELU) {
                v0.x = fmaxf(v0.x, 0.f); v0.y = fmaxf(v0.y, 0.f);
                v1.x = fmaxf(v1.x, 0.f); v1.y = fmaxf(v1.y, 0.f);
            }
            if (row0 < M)     *(float2*)(C + (size_t)row0 * BN + col)       = v0;
            if (row0 + 8 < M) *(float2*)(C + (size_t)(row0 + 8) * BN + col) = v1;
        }
    }
}

// ============ GEMM variant 1: fp32 A (split on the fly), BK=32 ============
template<int BN, bool RELU, bool BIAS>
__global__ void __launch_bounds__(256, 2)
mma_gemm_f32(const float* __restrict__ A,
             const __half* __restrict__ Bhi, const __half* __restrict__ Blo,
             const float* __restrict__ bias, float* __restrict__ C,
             int M, int K)
{
    constexpr int BM = 128, BK = 32;
    constexpr int WN = BN / 4;
    constexpr int NF = WN / 8;
    constexpr int ASZ = BM * BKP;                   // halves
    constexpr int BSZ = BN * BKP;
    constexpr int BB = BSZ * 2;

    extern __shared__ __half smh[];
    __half* AHp = smh;
    __half* ALp = smh + 2 * ASZ;
    const uint32_t sb  = smem_to_u32(smh);
    const uint32_t uAH = sb;
    const uint32_t uAL = sb + 2 * AB_BYTES;
    const uint32_t uBH = sb + 4 * AB_BYTES;
    const uint32_t uBL = sb + 4 * AB_BYTES + 2 * BB;

    const int tid  = threadIdx.x;
    const int lane = tid & 31;
    const int wid  = tid >> 5;
    const int wm   = (wid >> 2) * 64;
    const int wn   = (wid & 3) * WN;
    const int blockM = blockIdx.x * BM;

    const int a_r  = lane & 15, a_kc = lane >> 4;
    const int b_r  = (lane & 7) + ((lane >> 4) << 3);
    const int b_kc = (lane >> 3) & 1;

    float acc[4][NF][4];
    #pragma unroll
    for (int mf = 0; mf < 4; mf++)
        #pragma unroll
        for (int nf = 0; nf < NF; nf++)
            #pragma unroll
            for (int q = 0; q < 4; q++) acc[mf][nf][q] = 0.0f;

    const int nit = K / BK;

    auto fillB = [&](int i, int b) {
        constexpr int CH = BN * 4;
        #pragma unroll
        for (int it = 0; it < (CH + 255) / 256; it++) {
            int id = tid + it * 256;
            if (CH % 256 == 0 || id < CH) {
                int n = id >> 2, c = id & 3;
                uint32_t off = (uint32_t)b * BB + (uint32_t)n * (BKP * 2) + c * 16;
                cp_async16(uBH + off, Bhi + (size_t)n * K + i * BK + c * 8);
                cp_async16(uBL + off, Blo + (size_t)n * K + i * BK + c * 8);
            }
        }
    };
    float4 aR[4];
    auto loadA = [&](int i) {
        #pragma unroll
        for (int it = 0; it < 4; it++) {
            int id  = tid + it * 256;           // BM*8 f4-chunks = 1024
            int row = id >> 3, c4 = id & 7;
            int gr  = blockM + row;
            float4 v = make_float4(0.f, 0.f, 0.f, 0.f);
            if (gr < M)
                v = *(const float4*)(A + (size_t)gr * K + i * BK + c4 * 4);
            aR[it] = v;
        }
    };
    auto storeA = [&](int b) {
        #pragma unroll
        for (int it = 0; it < 4; it++) {
            int id  = tid + it * 256;
            int row = id >> 3, c4 = id & 7;
            float4 v = aR[it];
            __half hx, lx, hy, ly, hz, lz, hw, lw;
            split_f16(v.x, hx, lx); split_f16(v.y, hy, ly);
            split_f16(v.z, hz, lz); split_f16(v.w, hw, lw);
            int off = b * ASZ + row * BKP + c4 * 4;
            ((half2*)(AHp + off))[0] = __halves2half2(hx, hy);
            ((half2*)(AHp + off))[1] = __halves2half2(hz, hw);
            ((half2*)(ALp + off))[0] = __halves2half2(lx, ly);
            ((half2*)(ALp + off))[1] = __halves2half2(lz, lw);
        }
    };

    // prologue
    loadA(0);
    storeA(0);
    fillB(0, 0);
    cp_commit();

    // race-free mainloop
    for (int i = 0; i < nit; i++) {
        const int b = i & 1;
        cp_wait<0>();
        __syncthreads();
        if (i + 1 < nit) {
            fillB(i + 1, b ^ 1);
            cp_commit();
            loadA(i + 1);
        }
        gemm_compute<BN, NF>(uAH, uAL, uBH, uBL, b, wm, wn, a_r, a_kc, b_r, b_kc, acc);
        if (i + 1 < nit) storeA(b ^ 1);
    }

    gemm_epilogue<BN, NF, RELU, BIAS>(acc, bias, C, M, blockM, wm, wn, lane);
}

// ======= GEMM variant 2: pre-split fp16 A (pure cp.async), BK=32 =======
template<int BN>
__global__ void __launch_bounds__(256, 2)
mma_gemm_f16(const __half* __restrict__ Ahi, const __half* __restrict__ Alo,
             const __half* __restrict__ Bhi, const __half* __restrict__ Blo,
             float* __restrict__ C, int M, int K)
{
    constexpr int BM = 128, BK = 32;
    constexpr int WN = BN / 4;
    constexpr int NF = WN / 8;
    constexpr int BSZ = BN * BKP;
    constexpr int BB = BSZ * 2;

    extern __shared__ __half smh[];
    const uint32_t sb  = smem_to_u32(smh);
    const uint32_t uAH = sb;
    const uint32_t uAL = sb + 2 * AB_BYTES;
    const uint32_t uBH = sb + 4 * AB_BYTES;
    const uint32_t uBL = sb + 4 * AB_BYTES + 2 * BB;

    const int tid  = threadIdx.x;
    const int lane = tid & 31;
    const int wid  = tid >> 5;
    const int wm   = (wid >> 2) * 64;
    const int wn   = (wid & 3) * WN;
    const int blockM = blockIdx.x * BM;

    const int a_r  = lane & 15, a_kc = lane >> 4;
    const int b_r  = (lane & 7) + ((lane >> 4) << 3);
    const int b_kc = (lane >> 3) & 1;

    float acc[4][NF][4];
    #pragma unroll
    for (int mf = 0; mf < 4; mf++)
        #pragma unroll
        for (int nf = 0; nf < NF; nf++)
            #pragma unroll
            for (int q = 0; q < 4; q++) acc[mf][nf][q] = 0.0f;

    const int nit = K / BK;

    auto fillA = [&](int i, int b) {
        constexpr int CH = BM * 4;          // 16B chunks per component
        #pragma unroll
        for (int it = 0; it < CH / 256; it++) {
            int id = tid + it * 256;
            int row = id >> 2, c = id & 3;
            int gr = blockM + row;
            if (gr < M) {
                uint32_t off = (uint32_t)b * AB_BYTES + (uint32_t)row * (BKP * 2) + c * 16;
                cp_async16(uAH + off, Ahi + (size_t)gr * K + i * BK + c * 8);
                cp_async16(uAL + off, Alo + (size_t)gr * K + i * BK + c * 8);
            }
        }
    };
    auto fillB = [&](int i, int b) {
        constexpr int CH = BN * 4;
        #pragma unroll
        for (int it = 0; it < (CH + 255) / 256; it++) {
            int id = tid + it * 256;
            if (CH % 256 == 0 || id < CH) {
                int n = id >> 2, c = id & 3;
                uint32_t off = (uint32_t)b * BB + (uint32_t)n * (BKP * 2) + c * 16;
                cp_async16(uBH + off, Bhi + (size_t)n * K + i * BK + c * 8);
                cp_async16(uBL + off, Blo + (size_t)n * K + i * BK + c * 8);
            }
        }
    };

    // prologue
    fillA(0, 0);
    fillB(0, 0);
    cp_commit();

    for (int i = 0; i < nit; i++) {
        const int b = i & 1;
        cp_wait<0>();
        __syncthreads();
        if (i + 1 < nit) {
            fillA(i + 1, b ^ 1);
            fillB(i + 1, b ^ 1);
            cp_commit();
        }
        gemm_compute<BN, NF>(uAH, uAL, uBH, uBL, b, wm, wn, a_r, a_kc, b_r, b_kc, acc);
    }

    gemm_epilogue<BN, NF, false, false>(acc, nullptr, C, M, blockM, wm, wn, lane);
}

// ---------------- launch ----------------
extern "C" void kernel_launch(void* const* d_in, const int* in_sizes, int n_in,
                              void* d_out, int out_size)
{
    const float* x  = (const float*)d_in[0];
    const int*   ei = (const int*)  d_in[1];
    const float* w1 = (const float*)d_in[2];
    const float* b1 = (const float*)d_in[3];
    const float* cw = (const float*)d_in[4];
    const float* w2 = (const float*)d_in[5];
    const float* b2 = (const float*)d_in[6];

    float* out    = (float*)d_out;
    float* hout   = out;
    float* logits = out + (size_t)NN * HD;

    float *p_h0, *p_h;
    __half *p_chi, *p_clo;
    __half *p_w1h, *p_w1l, *p_cwh, *p_cwl, *p_w2h, *p_w2l;
    cudaGetSymbolAddress((void**)&p_h0,  g_h0);
    cudaGetSymbolAddress((void**)&p_h,   g_h);
    cudaGetSymbolAddress((void**)&p_chi, g_comb_hi);
    cudaGetSymbolAddress((void**)&p_clo, g_comb_lo);
    cudaGetSymbolAddress((void**)&p_w1h, g_w1t_hi);
    cudaGetSymbolAddress((void**)&p_w1l, g_w1t_lo);
    cudaGetSymbolAddress((void**)&p_cwh, g_cwt_hi);
    cudaGetSymbolAddress((void**)&p_cwl, g_cwt_lo);
    cudaGetSymbolAddress((void**)&p_w2h, g_w2t_hi);
    cudaGetSymbolAddress((void**)&p_w2l, g_w2t_lo);

    const int TPB = 256;
    const int gemm_grid = (NN + 127) / 128;                    // 782
    const int NBLK = (NN + 1023) / 1024;                       // 98
    const int SMEM_128 = 4 * AB_BYTES + 4 * 128 * BKP * 2;     // 81920 B
    const int SMEM_64  = 4 * AB_BYTES + 4 * 64 * BKP * 2;      // 61440 B

    cudaFuncSetAttribute(mma_gemm_f32<128, true, true>,
                         cudaFuncAttributeMaxDynamicSharedMemorySize, SMEM_128);
    cudaFuncSetAttribute(mma_gemm_f16<128>,
                         cudaFuncAttributeMaxDynamicSharedMemorySize, SMEM_128);
    cudaFuncSetAttribute(mma_gemm_f32<64, false, true>,
                         cudaFuncAttributeMaxDynamicSharedMemorySize, SMEM_64);

    // launches 1-3, then gemm1 as launch #4 (profiler capture slot)
    cnt_init_kernel <<<(NN + TPB - 1) / TPB, TPB>>>();
    cnt_accum_kernel<<<(NE + TPB - 1) / TPB, TPB>>>(ei);
    prep_weights    <<<(HD*DIN + 2*HD*HD + DOUT*HD + TPB - 1) / TPB, TPB>>>(w1, cw, w2);

    // h0 = relu(x @ w1 + b1)   [launch #4 -> profiled]
    mma_gemm_f32<128, true, true><<<gemm_grid, 256, SMEM_128>>>(
        x, p_w1h, p_w1l, b1, p_h0, NN, DIN);

    // rest of CSR build
    scan1_kernel    <<<NBLK, 1024>>>();
    scan2_kernel    <<<1, 128>>>(NBLK);
    fin_kernel      <<<(NN + TPB - 1) / TPB, TPB>>>();
    scatter_kernel  <<<(NE + TPB - 1) / TPB, TPB>>>(ei);

    // ---- layer 1: agg(h0) + combine + split -> comb; h = comb @ cw0 ----
    agg_kernel<<<(NN * 32 + TPB - 1) / TPB, TPB>>>(p_h0);
    mma_gemm_f16<128><<<gemm_grid, 256, SMEM_128>>>(
        p_chi, p_clo, p_cwh, p_cwl, p_h, NN, HD);

    // ---- layer 2: agg(h) + combine + split -> comb; hout = comb @ cw1 ----
    agg_kernel<<<(NN * 32 + TPB - 1) / TPB, TPB>>>(p_h);
    mma_gemm_f16<128><<<gemm_grid, 256, SMEM_128>>>(
        p_chi, p_clo, p_cwh + HD * HD, p_cwl + HD * HD, hout, NN, HD);

    // logits = hout @ w2 + b2
    mma_gemm_f32<64, false, true><<<gemm_grid, 256, SMEM_64>>>(
        hout, p_w2h, p_w2l, b2, logits, NN, HD);
}